// round 5
// baseline (speedup 1.0000x reference)
#include <cuda_runtime.h>
#include <cstdint>

#define ALPHA 16.0f
#define DDIM  1024
#define MROWS 16384   // B*S

// ---------------- scratch (no cudaMalloc allowed) ----------------
__device__ float g_E[DDIM * DDIM];      // tf32-rounded E[d][o]

// ---------------- helpers ----------------
__device__ __forceinline__ uint32_t smem_u32(const void* p) {
    uint32_t a;
    asm("{ .reg .u64 t; cvta.to.shared.u64 t, %1; cvt.u32.u64 %0, t; }" : "=r"(a) : "l"(p));
    return a;
}
__device__ __forceinline__ float to_tf32_f(float v) {
    asm("cvt.rna.tf32.f32 %0, %1;" : "=f"(v) : "f"(v));
    return v;
}
__device__ __forceinline__ uint32_t to_tf32_u(float f) {
    uint32_t u;
    asm("cvt.rna.tf32.f32 %0, %1;" : "=r"(u) : "f"(f));
    return u;
}
__device__ __forceinline__ void cp16(void* dst_smem, const void* src) {
    uint32_t d = smem_u32(dst_smem);
    asm volatile("cp.async.cg.shared.global [%0], [%1], 16;" :: "r"(d), "l"(src) : "memory");
}
#define CP_COMMIT()  asm volatile("cp.async.commit_group;" ::: "memory")
#define CP_WAIT(n)   asm volatile("cp.async.wait_group %0;" :: "n"(n) : "memory")

__device__ __forceinline__ void mma_tf32(float* c, const uint32_t* a, const uint32_t* b) {
    asm volatile(
        "mma.sync.aligned.m16n8k8.row.col.f32.tf32.tf32.f32 "
        "{%0,%1,%2,%3}, {%4,%5,%6,%7}, {%8,%9}, {%0,%1,%2,%3};"
        : "+f"(c[0]), "+f"(c[1]), "+f"(c[2]), "+f"(c[3])
        : "r"(a[0]), "r"(a[1]), "r"(a[2]), "r"(a[3]), "r"(b[0]), "r"(b[1]));
}

// ---------------------------------------------------------------------------
// Kernel 1 (fused): per 32x32 tile of E, fold the TT cores (tiny, redundant
// per block) and emit E[d][o] = tf32( W[o][d] + ALPHA * Left[d,:]@Right[:,o] ).
// W read coalesced via smem transpose tile; E written coalesced.
// ---------------------------------------------------------------------------
__global__ __launch_bounds__(256)
void build_E_fused(const float* __restrict__ W,
                   const float* __restrict__ c0, const float* __restrict__ c1,
                   const float* __restrict__ c2, const float* __restrict__ c3,
                   const float* __restrict__ c4, const float* __restrict__ c5) {
    __shared__ float C0[64], C1[1024], C2[512], C3[512], C4[1024], C5[64];
    __shared__ float P[1024], S1[1024];
    __shared__ float Lt[32 * 8], Rt[8 * 32];
    __shared__ float Wt[32 * 33];
    const int t  = threadIdx.x;
    const int bd = blockIdx.x;    // d-tile
    const int bo = blockIdx.y;    // o-tile

    for (int i = t; i < 64;   i += 256) C0[i] = c0[i];
    for (int i = t; i < 1024; i += 256) C1[i] = c1[i];
    for (int i = t; i < 512;  i += 256) C2[i] = c2[i];
    for (int i = t; i < 512;  i += 256) C3[i] = c3[i];
    for (int i = t; i < 1024; i += 256) C4[i] = c4[i];
    for (int i = t; i < 64;   i += 256) C5[i] = c5[i];
    // W tile, coalesced: lane -> d, row -> o; store transposed-access-friendly
    #pragma unroll
    for (int p = 0; p < 4; p++) {
        int j = t + p * 256;
        int oi = j >> 5, di = j & 31;
        Wt[oi * 33 + di] = W[(size_t)(bo * 32 + oi) * 1024 + bd * 32 + di];
    }
    __syncthreads();

    #pragma unroll
    for (int p = 0; p < 4; p++) {
        int i = t + p * 256;
        int b = i & 7, m2 = (i >> 3) & 15, m1 = i >> 7;
        float s = 0.f;
        #pragma unroll
        for (int a = 0; a < 8; a++) s += C0[m1 * 8 + a] * C1[(a * 16 + m2) * 8 + b];
        P[i] = s;
    }
    #pragma unroll
    for (int p = 0; p < 4; p++) {
        int i = t + p * 256;
        int n3 = i & 7, n2 = (i >> 3) & 15, e = i >> 7;
        float s = 0.f;
        #pragma unroll
        for (int f = 0; f < 8; f++) s += C4[(e * 16 + n2) * 8 + f] * C5[f * 8 + n3];
        S1[i] = s;
    }
    __syncthreads();

    {   // Left rows for this d-tile: 32x8, one elem/thread
        int di = t >> 3, c = t & 7;
        int d = bd * 32 + di;
        int m1 = d & 7, m2 = (d >> 3) & 15, m3 = d >> 7;
        float s = 0.f;
        #pragma unroll
        for (int b = 0; b < 8; b++) s += P[(m1 * 16 + m2) * 8 + b] * C2[(b * 8 + m3) * 8 + c];
        Lt[di * 8 + c] = s;
    }
    {   // Right cols for this o-tile: 8x32, one elem/thread
        int c = t >> 5, oi = t & 31;
        int o = bo * 32 + oi;
        int n3 = o & 7, n2 = (o >> 3) & 15, n1 = o >> 7;
        float s = 0.f;
        #pragma unroll
        for (int e = 0; e < 8; e++) s += C3[(c * 8 + n1) * 8 + e] * S1[(e * 16 + n2) * 8 + n3];
        Rt[c * 32 + oi] = s;
    }
    __syncthreads();

    #pragma unroll
    for (int p = 0; p < 4; p++) {
        int j = t + p * 256;
        int di = j >> 5, oi = j & 31;
        float s = 0.f;
        #pragma unroll
        for (int c = 0; c < 8; c++) s += Lt[di * 8 + c] * Rt[c * 32 + oi];
        g_E[(size_t)(bd * 32 + di) * 1024 + bo * 32 + oi] =
            to_tf32_f(Wt[oi * 33 + di] + ALPHA * s);
    }
}

// ---------------------------------------------------------------------------
// Kernel 2: tf32 mma.sync GEMM. C[16384,1024] = X @ E + bias.
// BM=256, BN=128, BK=32. 256 threads, 8 warps (4x2), warp tile 64x64 (mt=4).
// 3-stage cp.async pipeline, one __syncthreads per chunk.
// A smem [256][36] (pad 4 -> frag banks 4g+tig, conflict-free)
// B smem [32][136]  (pad 8 -> frag banks 8*tig+g, conflict-free)
// ---------------------------------------------------------------------------
#define ASTRIDE 36
#define BSTRIDE 136
#define A_STG   (256 * ASTRIDE)
#define B_STG   (32 * BSTRIDE)
#define STAGES  3
#define NCHUNK  32

__global__ __launch_bounds__(256, 1)
void gemm_tf32(const float* __restrict__ X, const float* __restrict__ bias,
               float* __restrict__ out) {
    extern __shared__ float sm[];
    float* As = sm;
    float* Bs = sm + STAGES * A_STG;

    const int t    = threadIdx.x;
    const int wid  = t >> 5;
    const int lane = t & 31;
    const int g    = lane >> 2;     // 0..7
    const int tig  = lane & 3;      // 0..3
    const int wm   = wid >> 1;      // 0..3  (64-row band)
    const int wn   = wid & 1;       // 0..1  (64-col band)
    const int bx   = blockIdx.x;    // N tile (0..7)
    const int by   = blockIdx.y;    // M tile (0..63)

    const float* Xb = X + (size_t)(by * 256) * 1024;
    const float* Eb = g_E + bx * 128;

    float acc[4][8][4];
    #pragma unroll
    for (int mt = 0; mt < 4; mt++)
        #pragma unroll
        for (int nt = 0; nt < 8; nt++)
            #pragma unroll
            for (int i = 0; i < 4; i++) acc[mt][nt][i] = 0.f;

    auto load_stage = [&](int s, int kc) {
        float* Ad = As + s * A_STG;
        float* Bd = Bs + s * B_STG;
        #pragma unroll
        for (int p = 0; p < 8; p++) {           // A: 256x32
            int qi = t + p * 256;
            int row = qi >> 3, quad = qi & 7;
            cp16(Ad + row * ASTRIDE + quad * 4,
                 Xb + (size_t)row * 1024 + kc + quad * 4);
        }
        #pragma unroll
        for (int p = 0; p < 4; p++) {           // B: 32x128
            int qi = t + p * 256;
            int row = qi >> 5, quad = qi & 31;
            cp16(Bd + row * BSTRIDE + quad * 4,
                 Eb + (size_t)(kc + row) * 1024 + quad * 4);
        }
    };

    load_stage(0, 0);  CP_COMMIT();
    load_stage(1, 32); CP_COMMIT();

    for (int c = 0; c < NCHUNK; c++) {
        if (c == NCHUNK - 1) { CP_WAIT(0); } else { CP_WAIT(1); }
        __syncthreads();   // stage c visible; all warps done with stage (c-1)

        if (c + 2 < NCHUNK) {            // issue next-next load, 2 in flight
            load_stage((c + 2) % STAGES, (c + 2) * 32);
            CP_COMMIT();
        }

        const float* Ab = As + (c % STAGES) * A_STG;
        const float* Bb = Bs + (c % STAGES) * B_STG;

        #pragma unroll
        for (int ks = 0; ks < 4; ks++) {
            const int k = ks * 8;
            uint32_t af[4][4];
            #pragma unroll
            for (int mt = 0; mt < 4; mt++) {
                int m = wm * 64 + mt * 16;
                af[mt][0] = to_tf32_u(Ab[(m + g)     * ASTRIDE + k + tig]);
                af[mt][1] = to_tf32_u(Ab[(m + g + 8) * ASTRIDE + k + tig]);
                af[mt][2] = to_tf32_u(Ab[(m + g)     * ASTRIDE + k + tig + 4]);
                af[mt][3] = to_tf32_u(Ab[(m + g + 8) * ASTRIDE + k + tig + 4]);
            }
            #pragma unroll
            for (int nt = 0; nt < 8; nt++) {
                int n = wn * 64 + nt * 8;
                uint32_t bf[2];
                bf[0] = __float_as_uint(Bb[(k + tig)     * BSTRIDE + n + g]);
                bf[1] = __float_as_uint(Bb[(k + tig + 4) * BSTRIDE + n + g]);
                #pragma unroll
                for (int mt = 0; mt < 4; mt++) mma_tf32(acc[mt][nt], af[mt], bf);
            }
        }
    }

    // ---- epilogue: bias add, direct stores ----
    #pragma unroll
    for (int mt = 0; mt < 4; mt++) {
        int row0 = by * 256 + wm * 64 + mt * 16 + g;
        #pragma unroll
        for (int nt = 0; nt < 8; nt++) {
            int col = bx * 128 + wn * 64 + nt * 8 + tig * 2;
            float b0 = bias[col], b1 = bias[col + 1];
            float2 v0 = { acc[mt][nt][0] + b0, acc[mt][nt][1] + b1 };
            float2 v1 = { acc[mt][nt][2] + b0, acc[mt][nt][3] + b1 };
            *(float2*)(out + (size_t)row0 * 1024 + col)       = v0;
            *(float2*)(out + (size_t)(row0 + 8) * 1024 + col) = v1;
        }
    }
}

// ---------------------------------------------------------------------------
extern "C" void kernel_launch(void* const* d_in, const int* in_sizes, int n_in,
                              void* d_out, int out_size) {
    const float* x  = (const float*)d_in[0];
    const float* W  = (const float*)d_in[1];
    const float* b  = (const float*)d_in[2];
    const float* c0 = (const float*)d_in[3];
    const float* c1 = (const float*)d_in[4];
    const float* c2 = (const float*)d_in[5];
    const float* c3 = (const float*)d_in[6];
    const float* c4 = (const float*)d_in[7];
    const float* c5 = (const float*)d_in[8];
    float* out = (float*)d_out;

    dim3 bgrid(32, 32);
    build_E_fused<<<bgrid, 256>>>(W, c0, c1, c2, c3, c4, c5);

    const int smem_bytes = STAGES * (A_STG + B_STG) * 4;   // ~159 KB
    cudaFuncSetAttribute(gemm_tf32, cudaFuncAttributeMaxDynamicSharedMemorySize, smem_bytes);
    dim3 grid(8, 64);   // (N tiles, M tiles), bx fastest: concurrent CTAs share A band
    gemm_tf32<<<grid, 256, smem_bytes>>>(x, b, out);
}

// round 6
// speedup vs baseline: 1.1911x; 1.1911x over previous
#include <cuda_runtime.h>
#include <cstdint>

#define ALPHA 16.0f
#define DDIM  1024
#define MROWS 16384   // B*S

// ---------------- scratch (no cudaMalloc allowed) ----------------
__device__ float g_E[DDIM * DDIM];      // tf32-rounded E[d][o]

// ---------------- helpers ----------------
__device__ __forceinline__ uint32_t smem_u32(const void* p) {
    uint32_t a;
    asm("{ .reg .u64 t; cvta.to.shared.u64 t, %1; cvt.u32.u64 %0, t; }" : "=r"(a) : "l"(p));
    return a;
}
__device__ __forceinline__ float to_tf32_f(float v) {
    asm("cvt.rna.tf32.f32 %0, %1;" : "=f"(v) : "f"(v));
    return v;
}
__device__ __forceinline__ uint32_t to_tf32_u(float f) {
    uint32_t u;
    asm("cvt.rna.tf32.f32 %0, %1;" : "=r"(u) : "f"(f));
    return u;
}
__device__ __forceinline__ void cp16(void* dst_smem, const void* src) {
    uint32_t d = smem_u32(dst_smem);
    asm volatile("cp.async.cg.shared.global [%0], [%1], 16;" :: "r"(d), "l"(src) : "memory");
}
#define CP_COMMIT()  asm volatile("cp.async.commit_group;" ::: "memory")
#define CP_WAIT(n)   asm volatile("cp.async.wait_group %0;" :: "n"(n) : "memory")

__device__ __forceinline__ void mma_tf32(float* c, const uint32_t* a, const uint32_t* b) {
    asm volatile(
        "mma.sync.aligned.m16n8k8.row.col.f32.tf32.tf32.f32 "
        "{%0,%1,%2,%3}, {%4,%5,%6,%7}, {%8,%9}, {%0,%1,%2,%3};"
        : "+f"(c[0]), "+f"(c[1]), "+f"(c[2]), "+f"(c[3])
        : "r"(a[0]), "r"(a[1]), "r"(a[2]), "r"(a[3]), "r"(b[0]), "r"(b[1]));
}

// ---------------------------------------------------------------------------
// Kernel 1 (fused): per 64x64 tile of E, fold the TT cores (tiny, redundant
// per block) and emit E[d][o] = tf32( W[o][d] + ALPHA * Left[d,:]@Right[:,o] ).
// W read coalesced via smem transpose tile; E written coalesced.
// ---------------------------------------------------------------------------
__global__ __launch_bounds__(256)
void build_E_fused(const float* __restrict__ W,
                   const float* __restrict__ c0, const float* __restrict__ c1,
                   const float* __restrict__ c2, const float* __restrict__ c3,
                   const float* __restrict__ c4, const float* __restrict__ c5) {
    __shared__ float C0[64], C1[1024], C2[512], C3[512], C4[1024], C5[64];
    __shared__ float P[1024], S1[1024];
    __shared__ float Lt[64 * 8], Rt[8 * 64];
    __shared__ float Wt[64 * 65];
    const int t  = threadIdx.x;
    const int bd = blockIdx.x;    // d-tile (64 wide)
    const int bo = blockIdx.y;    // o-tile (64 wide)

    for (int i = t; i < 64;   i += 256) C0[i] = c0[i];
    for (int i = t; i < 1024; i += 256) C1[i] = c1[i];
    for (int i = t; i < 512;  i += 256) C2[i] = c2[i];
    for (int i = t; i < 512;  i += 256) C3[i] = c3[i];
    for (int i = t; i < 1024; i += 256) C4[i] = c4[i];
    for (int i = t; i < 64;   i += 256) C5[i] = c5[i];
    // W tile, coalesced over d
    #pragma unroll
    for (int p = 0; p < 16; p++) {
        int j = t + p * 256;
        int oi = j >> 6, di = j & 63;
        Wt[oi * 65 + di] = W[(size_t)(bo * 64 + oi) * 1024 + bd * 64 + di];
    }
    __syncthreads();

    #pragma unroll
    for (int p = 0; p < 4; p++) {
        int i = t + p * 256;
        int b = i & 7, m2 = (i >> 3) & 15, m1 = i >> 7;
        float s = 0.f;
        #pragma unroll
        for (int a = 0; a < 8; a++) s += C0[m1 * 8 + a] * C1[(a * 16 + m2) * 8 + b];
        P[i] = s;
    }
    #pragma unroll
    for (int p = 0; p < 4; p++) {
        int i = t + p * 256;
        int n3 = i & 7, n2 = (i >> 3) & 15, e = i >> 7;
        float s = 0.f;
        #pragma unroll
        for (int f = 0; f < 8; f++) s += C4[(e * 16 + n2) * 8 + f] * C5[f * 8 + n3];
        S1[i] = s;
    }
    __syncthreads();

    #pragma unroll
    for (int p = 0; p < 2; p++) {   // Left rows for this d-tile: 64x8
        int j = t + p * 256;
        int di = j >> 3, c = j & 7;
        int d = bd * 64 + di;
        int m1 = d & 7, m2 = (d >> 3) & 15, m3 = d >> 7;
        float s = 0.f;
        #pragma unroll
        for (int b = 0; b < 8; b++) s += P[(m1 * 16 + m2) * 8 + b] * C2[(b * 8 + m3) * 8 + c];
        Lt[di * 8 + c] = s;
    }
    #pragma unroll
    for (int p = 0; p < 2; p++) {   // Right cols for this o-tile: 8x64
        int j = t + p * 256;
        int c = j >> 6, oi = j & 63;
        int o = bo * 64 + oi;
        int n3 = o & 7, n2 = (o >> 3) & 15, n1 = o >> 7;
        float s = 0.f;
        #pragma unroll
        for (int e = 0; e < 8; e++) s += C3[(c * 8 + n1) * 8 + e] * S1[(e * 16 + n2) * 8 + n3];
        Rt[c * 64 + oi] = s;
    }
    __syncthreads();

    #pragma unroll
    for (int p = 0; p < 16; p++) {
        int j = t + p * 256;
        int di = j >> 6, oi = j & 63;
        float s = 0.f;
        #pragma unroll
        for (int c = 0; c < 8; c++) s += Lt[di * 8 + c] * Rt[c * 64 + oi];
        g_E[(size_t)(bd * 64 + di) * 1024 + bo * 64 + oi] =
            to_tf32_f(Wt[oi * 65 + di] + ALPHA * s);
    }
}

// ---------------------------------------------------------------------------
// Kernel 2: tf32 mma.sync GEMM. C[16384,1024] = X @ E + bias.
// BM=128, BN=128, BK=32. 256 threads, 8 warps (4x2), warp tile 32x64.
// __launch_bounds__(256,2) -> <=128 regs -> 2 CTAs/SM, 16 warps/SM.
// 3-stage cp.async pipeline, ONE __syncthreads per chunk, 2 loads in flight.
// A smem [128][36] (pad 4 -> frag banks 4g+tig, conflict-free)
// B smem [32][136] (pad 8 -> frag banks 8*tig+g, conflict-free)
// ---------------------------------------------------------------------------
#define ASTRIDE 36
#define BSTRIDE 136
#define A_STG   (128 * ASTRIDE)
#define B_STG   (32 * BSTRIDE)
#define STAGES  3
#define NCHUNK  32

__global__ __launch_bounds__(256, 2)
void gemm_tf32(const float* __restrict__ X, const float* __restrict__ bias,
               float* __restrict__ out) {
    extern __shared__ float sm[];
    float* As = sm;
    float* Bs = sm + STAGES * A_STG;

    const int t    = threadIdx.x;
    const int wid  = t >> 5;
    const int lane = t & 31;
    const int g    = lane >> 2;     // 0..7
    const int tig  = lane & 3;      // 0..3
    const int wm   = wid >> 1;      // 0..3  (32-row band)
    const int wn   = wid & 1;       // 0..1  (64-col band)
    const int bx   = blockIdx.x;    // N tile (0..7)
    const int by   = blockIdx.y;    // M tile (0..127)

    const float* Xb = X + (size_t)(by * 128) * 1024;
    const float* Eb = g_E + bx * 128;

    float acc[2][8][4];
    #pragma unroll
    for (int mt = 0; mt < 2; mt++)
        #pragma unroll
        for (int nt = 0; nt < 8; nt++)
            #pragma unroll
            for (int i = 0; i < 4; i++) acc[mt][nt][i] = 0.f;

    auto load_stage = [&](int s, int kc) {
        float* Ad = As + s * A_STG;
        float* Bd = Bs + s * B_STG;
        #pragma unroll
        for (int p = 0; p < 4; p++) {           // A: 128x32
            int qi = t + p * 256;
            int row = qi >> 3, quad = qi & 7;
            cp16(Ad + row * ASTRIDE + quad * 4,
                 Xb + (size_t)row * 1024 + kc + quad * 4);
        }
        #pragma unroll
        for (int p = 0; p < 4; p++) {           // B: 32x128
            int qi = t + p * 256;
            int row = qi >> 5, quad = qi & 31;
            cp16(Bd + row * BSTRIDE + quad * 4,
                 Eb + (size_t)(kc + row) * 1024 + quad * 4);
        }
    };

    load_stage(0, 0);  CP_COMMIT();
    load_stage(1, 32); CP_COMMIT();

    for (int c = 0; c < NCHUNK; c++) {
        if (c == NCHUNK - 1) { CP_WAIT(0); } else { CP_WAIT(1); }
        __syncthreads();   // stage c visible; all warps done with stage c-1's slot

        if (c + 2 < NCHUNK) {            // keep 2 loads in flight
            load_stage((c + 2) % STAGES, (c + 2) * 32);
            CP_COMMIT();
        }

        const float* Ab = As + (c % STAGES) * A_STG;
        const float* Bb = Bs + (c % STAGES) * B_STG;

        #pragma unroll
        for (int ks = 0; ks < 4; ks++) {
            const int k = ks * 8;
            uint32_t af[2][4];
            #pragma unroll
            for (int mt = 0; mt < 2; mt++) {
                int m = wm * 32 + mt * 16;
                af[mt][0] = to_tf32_u(Ab[(m + g)     * ASTRIDE + k + tig]);
                af[mt][1] = to_tf32_u(Ab[(m + g + 8) * ASTRIDE + k + tig]);
                af[mt][2] = to_tf32_u(Ab[(m + g)     * ASTRIDE + k + tig + 4]);
                af[mt][3] = to_tf32_u(Ab[(m + g + 8) * ASTRIDE + k + tig + 4]);
            }
            #pragma unroll
            for (int nt = 0; nt < 8; nt++) {
                int n = wn * 64 + nt * 8;
                uint32_t bf[2];
                bf[0] = __float_as_uint(Bb[(k + tig)     * BSTRIDE + n + g]);
                bf[1] = __float_as_uint(Bb[(k + tig + 4) * BSTRIDE + n + g]);
                mma_tf32(acc[0][nt], af[0], bf);
                mma_tf32(acc[1][nt], af[1], bf);
            }
        }
    }

    // ---- epilogue: bias add, direct stores ----
    #pragma unroll
    for (int mt = 0; mt < 2; mt++) {
        int row0 = by * 128 + wm * 32 + mt * 16 + g;
        #pragma unroll
        for (int nt = 0; nt < 8; nt++) {
            int col = bx * 128 + wn * 64 + nt * 8 + tig * 2;
            float b0 = bias[col], b1 = bias[col + 1];
            float2 v0 = { acc[mt][nt][0] + b0, acc[mt][nt][1] + b1 };
            float2 v1 = { acc[mt][nt][2] + b0, acc[mt][nt][3] + b1 };
            *(float2*)(out + (size_t)row0 * 1024 + col)       = v0;
            *(float2*)(out + (size_t)(row0 + 8) * 1024 + col) = v1;
        }
    }
}

// ---------------------------------------------------------------------------
extern "C" void kernel_launch(void* const* d_in, const int* in_sizes, int n_in,
                              void* d_out, int out_size) {
    const float* x  = (const float*)d_in[0];
    const float* W  = (const float*)d_in[1];
    const float* b  = (const float*)d_in[2];
    const float* c0 = (const float*)d_in[3];
    const float* c1 = (const float*)d_in[4];
    const float* c2 = (const float*)d_in[5];
    const float* c3 = (const float*)d_in[6];
    const float* c4 = (const float*)d_in[7];
    const float* c5 = (const float*)d_in[8];
    float* out = (float*)d_out;

    dim3 bgrid(16, 16);
    build_E_fused<<<bgrid, 256>>>(W, c0, c1, c2, c3, c4, c5);

    const int smem_bytes = STAGES * (A_STG + B_STG) * 4;   // ~105 KB/CTA
    cudaFuncSetAttribute(gemm_tf32, cudaFuncAttributeMaxDynamicSharedMemorySize, smem_bytes);
    dim3 grid(8, 128);   // (N tiles, M tiles), bx fastest: concurrent CTAs share A band
    gemm_tf32<<<grid, 256, smem_bytes>>>(x, b, out);
}